// round 15
// baseline (speedup 1.0000x reference)
#include <cuda_runtime.h>

// Problem constants
#define NN 16000
#define EE 48000
#define FF 32000
#define GG 32
#define DD 64
#define BB 32
#define MM (NN + EE + FF)
#define HID 256
#define NC 10
#define FLATW (BB * DD)   // 2048

// ecc tiling
#define CS    128
#define ECC_Y 4
#define TPB   256
#define MAXCH ((MM + CS - 1) / CS + GG)   // 782
#define NROW  39           // 3 low pad + 32 + 4 high pad band rows
#define GPQ   4            // graphs per gemm block

// Sigmoid band constants (SIGA = 200/31)
#define C1f   1.577980e-3f   // e^{-SIGA}
#define C2f   2.490021e-6f   // e^{-2 SIGA}
#define EXP2K 9.3077108f     // SIGA * log2(e)

// Device scratch (zero-initialized at load; replay resets by k_gemm2)
__device__ float g_nh[NN * DD];
__device__ int4  g_items[MM];
__device__ int   g_hist[GG];
__device__ int   g_cursor2[GG];
__device__ float g_acc[GG * BB * DD];   // difference-domain accumulators
__device__ float g_h[GG * HID];

// ---------------------------------------------------------------------------
// Fused: nh (float4) + g_acc zero (float4) + graph histogram
#define NH_B 1000   // NN*16/256
#define Z_B  64     // GG*BB*DD/4/256
#define H_B  375    // ceil(MM/256)

__global__ void k_init(const float* __restrict__ x, const float* __restrict__ nw,
                       const float* __restrict__ v,
                       const int* __restrict__ ei, const int* __restrict__ fc,
                       const int* __restrict__ bid) {
    __shared__ int sh[GG];
    int b = blockIdx.x, tid = threadIdx.x;
    if (b < NH_B) {
        int t = b * 256 + tid;            // < NN*16
        int n = t >> 4, c4 = t & 15;
        const float4* vv = (const float4*)v;
        float4 v0 = vv[c4], v1 = vv[16 + c4], v2 = vv[32 + c4];
        float x0 = x[n * 3], x1 = x[n * 3 + 1], x2 = x[n * 3 + 2];
        float w = nw[n];
        float4 r;
        r.x = (x0 * v0.x + x1 * v1.x + x2 * v2.x) * w;
        r.y = (x0 * v0.y + x1 * v1.y + x2 * v2.y) * w;
        r.z = (x0 * v0.z + x1 * v1.z + x2 * v2.z) * w;
        r.w = (x0 * v0.w + x1 * v1.w + x2 * v2.w) * w;
        ((float4*)g_nh)[t] = r;
    } else if (b < NH_B + Z_B) {
        int t = (b - NH_B) * 256 + tid;
        ((float4*)g_acc)[t] = make_float4(0.f, 0.f, 0.f, 0.f);
    } else {
        if (tid < GG) sh[tid] = 0;
        __syncthreads();
        int t = (b - NH_B - Z_B) * 256 + tid;
        if (t < MM) {
            int g;
            if (t < NN)           g = bid[t];
            else if (t < NN + EE) g = bid[ei[t - NN]];
            else                  g = bid[fc[t - NN - EE]];
            atomicAdd(&sh[g], 1);
        }
        __syncthreads();
        if (tid < GG && sh[tid] > 0) atomicAdd(&g_hist[tid], sh[tid]);
    }
}

// Warp-wide inclusive scan over 32 lanes
__device__ __forceinline__ int wscan(int v, int lane) {
    #pragma unroll
    for (int s = 1; s < 32; s <<= 1) {
        int t = __shfl_up_sync(0xFFFFFFFFu, v, s);
        if (lane >= s) v += t;
    }
    return v;
}

// Counting-sort scatter; offsets computed by in-block warp scan of g_hist.
__global__ void k_scatter(const int* __restrict__ ei, const int* __restrict__ fc,
                          const int* __restrict__ bid,
                          const float* __restrict__ ew, const float* __restrict__ fw) {
    __shared__ int scnt[GG];
    __shared__ int sbase[GG];
    __shared__ int soff[GG];
    int tid = threadIdx.x;
    if (tid < 32) {
        int cnt = g_hist[tid];
        int v = wscan(cnt, tid);
        soff[tid] = v - cnt;
        scnt[tid] = 0;
    }
    __syncthreads();
    int t = blockIdx.x * blockDim.x + tid;
    int g = 0, lr = 0;
    int4 it = make_int4(0, 0, 0, 0);
    bool valid = (t < MM);
    if (valid) {
        if (t < NN) {
            g = bid[t];
            int tb = t << 8;
            it = make_int4(tb, tb, tb, __float_as_int(1.0f));
        } else if (t < NN + EE) {
            int e = t - NN;
            int a = ei[e], b = ei[EE + e];
            g = bid[a];
            it = make_int4(a << 8, b << 8, a << 8, __float_as_int(-ew[e]));
        } else {
            int q = t - NN - EE;
            int a = fc[q], b = fc[FF + q], c = fc[2 * FF + q];
            g = bid[a];
            it = make_int4(a << 8, b << 8, c << 8, __float_as_int(fw[q]));
        }
        lr = atomicAdd(&scnt[g], 1);
    }
    __syncthreads();
    if (tid < GG && scnt[tid] > 0)
        sbase[tid] = soff[tid] + atomicAdd(&g_cursor2[tid], scnt[tid]);
    __syncthreads();
    if (valid) g_items[sbase[g] + lr] = it;
}

// ECC kernel: row-major band (row stride 256 => bank = tid%32, conflict-free
// AND immediate-offset RMWs), 3 sigmoids, 4 difference-domain deltas.
__global__ void __launch_bounds__(TPB) k_ecc() {
    __shared__ float band[NROW * TPB];      // 39936 B, band[row*256 + tid]
    __shared__ int   sck[3];                // {g, start, end}

    int tid = threadIdx.x;
    float4* b4 = (float4*)band;
    for (int i = tid; i < NROW * TPB / 4; i += TPB) b4[i] = make_float4(0.f, 0.f, 0.f, 0.f);

    if (tid < 32) {
        int cnt = g_hist[tid];
        int v = wscan(cnt, tid);
        int off = v - cnt;
        int nch = (cnt + CS - 1) / CS;
        int c = wscan(nch, tid);
        int cb = c - nch;
        int bx = blockIdx.x;
        bool own = (bx >= cb) && (bx < cb + nch);
        unsigned m = __ballot_sync(0xFFFFFFFFu, own);
        if (m == 0) {
            if (tid == 0) { sck[0] = 0; sck[1] = 0; sck[2] = 0; }
        } else {
            int src  = __ffs(m) - 1;
            int offg = __shfl_sync(0xFFFFFFFFu, off, src);
            int cbg  = __shfl_sync(0xFFFFFFFFu, cb, src);
            int cntg = __shfl_sync(0xFFFFFFFFu, cnt, src);
            if (tid == 0) {
                int st = offg + (bx - cbg) * CS;
                sck[0] = src; sck[1] = st; sck[2] = min(st + CS, offg + cntg);
            }
        }
    }
    __syncthreads();
    int g = sck[0], start = sck[1], end = sck[2];
    if (start >= end) return;

    int d = tid & 63, y = tid >> 6;
    const char* nb = (const char*)g_nh + d * 4;
    float* base = band + tid;

    for (int i = start + y; i < end; i += ECC_Y) {
        int4 it = g_items[i];
        float s  = (it.w < 0) ? -1.f : 1.f;
        float wa = fabsf(__int_as_float(it.w));
        float h0 = *(const float*)(nb + it.x);
        float h1 = *(const float*)(nb + it.y);
        float h2 = *(const float*)(nb + it.z);
        float h  = fmaxf(h0, fmaxf(h1, h2)) * wa;

        float f  = fmaf(h, 15.5f, 15.5f);        // bump coordinate
        float bf = ceilf(f - 1.5f);              // band rows bf..bf+2
        int   p  = min(max((int)bf, -3), 31) + 3;// physical base row (pads absorb ends)
        float E  = exp2f((f - bf) * EXP2K);      // e^{SIGA*(f-bf)}
        float s0 = __fdividef(s, 1.f + E);       // s * sigmoid(row bf)
        float s1 = __fdividef(s, 1.f + E * C1f);
        float s2 = __fdividef(s, 1.f + E * C2f);

        float* a = base + p * TPB;               // one IMAD; imm offsets below
        a[0 * TPB] += s0;
        a[1 * TPB] += s1 - s0;
        a[2 * TPB] += s2 - s1;
        a[3 * TPB] += s  - s2;                   // saturation delta
    }
    __syncthreads();

    float* acc = g_acc + g * (BB * DD);
    for (int i = tid; i < BB * DD; i += TPB) {
        int b = i >> 6, dd = i & 63;
        float v = 0.f;
        #pragma unroll
        for (int y2 = 0; y2 < ECC_Y; y2++) {
            int t2 = y2 * 64 + dd;
            v += band[(b + 3) * TPB + t2];
            if (b == 0) v += band[t2] + band[TPB + t2] + band[2 * TPB + t2];
        }
        atomicAdd(&acc[i], v);
    }
}

// gemm1: finalize flat (inline) + first layer, 8 HID rows x 4 graphs per block,
// grid (32, 8) = 256 blocks — the R10-measured-best configuration, unfused.
__global__ void __launch_bounds__(256) k_gemm1(
        const float* __restrict__ W1, const float* __restrict__ b1,
        float* __restrict__ out, int flat_off) {
    __shared__ float sf[GPQ][FLATW];      // 32KB
    __shared__ float ss[GPQ][4][DD];
    int ht = blockIdx.x, gq = blockIdx.y;
    int tid = threadIdx.x;
    int d = tid & 63, q = tid >> 6;

    float vals[GPQ][8];
    #pragma unroll
    for (int gi = 0; gi < GPQ; gi++) {
        int g = gq * GPQ + gi;
        float run = 0.f;
        #pragma unroll
        for (int k = 0; k < 8; k++) {
            run += g_acc[(g * BB + q * 8 + k) * DD + d];
            vals[gi][k] = run;
        }
        ss[gi][q][d] = run;
    }
    __syncthreads();
    #pragma unroll
    for (int gi = 0; gi < GPQ; gi++) {
        float offp = 0.f;
        for (int r = 0; r < q; r++) offp += ss[gi][r][d];
        #pragma unroll
        for (int k = 0; k < 8; k++) {
            float fv = offp + vals[gi][k];
            sf[gi][(q * 8 + k) * DD + d] = fv;
            if (ht == 0 && flat_off >= 0)
                out[flat_off + (gq * GPQ + gi) * FLATW + (q * 8 + k) * DD + d] = fv;
        }
    }
    __syncthreads();

    int row_l = tid >> 5, lane = tid & 31;
    int row = ht * 8 + row_l;
    const float4* w1v = (const float4*)(W1 + row * FLATW);
    float a0 = 0.f, a1 = 0.f, a2 = 0.f, a3 = 0.f;
    #pragma unroll 4
    for (int j = 0; j < 16; j++) {
        float4 w  = w1v[j * 32 + lane];
        float4 fa = ((const float4*)sf[0])[j * 32 + lane];
        float4 fb = ((const float4*)sf[1])[j * 32 + lane];
        float4 fc2 = ((const float4*)sf[2])[j * 32 + lane];
        float4 fe = ((const float4*)sf[3])[j * 32 + lane];
        a0 += w.x * fa.x + w.y * fa.y + w.z * fa.z + w.w * fa.w;
        a1 += w.x * fb.x + w.y * fb.y + w.z * fb.z + w.w * fb.w;
        a2 += w.x * fc2.x + w.y * fc2.y + w.z * fc2.z + w.w * fc2.w;
        a3 += w.x * fe.x + w.y * fe.y + w.z * fe.z + w.w * fe.w;
    }
    #pragma unroll
    for (int sft = 16; sft >= 1; sft >>= 1) {
        a0 += __shfl_down_sync(0xFFFFFFFFu, a0, sft);
        a1 += __shfl_down_sync(0xFFFFFFFFu, a1, sft);
        a2 += __shfl_down_sync(0xFFFFFFFFu, a2, sft);
        a3 += __shfl_down_sync(0xFFFFFFFFu, a3, sft);
    }
    if (lane == 0) {
        float bb = b1[row];
        int gb = gq * GPQ;
        g_h[(gb + 0) * HID + row] = fmaxf(a0 + bb, 0.f);
        g_h[(gb + 1) * HID + row] = fmaxf(a1 + bb, 0.f);
        g_h[(gb + 2) * HID + row] = fmaxf(a2 + bb, 0.f);
        g_h[(gb + 3) * HID + row] = fmaxf(a3 + bb, 0.f);
    }
}

// gemm2: logits = h @ W2^T + b2. One block, 320 threads. Resets replay state.
__global__ void k_gemm2(const float* __restrict__ W2, const float* __restrict__ b2,
                        float* __restrict__ out, int logit_off) {
    __shared__ float sh[GG][HID + 1];
    __shared__ float sw[NC * HID];
    int tid = threadIdx.x;                // 320
    for (int i = tid; i < GG * HID; i += 320) sh[i >> 8][i & 255] = g_h[i];
    for (int i = tid; i < NC * HID; i += 320) sw[i] = W2[i];
    __syncthreads();
    int c = tid >> 5, g = tid & 31;       // c in 0..9
    float acc = b2[c];
    #pragma unroll 8
    for (int k = 0; k < HID; k++) acc += sh[g][k] * sw[c * HID + k];
    if (logit_off >= 0) out[logit_off + g * NC + c] = acc;
    if (tid < GG) { g_hist[tid] = 0; g_cursor2[tid] = 0; }   // reset for next replay
}

// ---------------------------------------------------------------------------
extern "C" void kernel_launch(void* const* d_in, const int* in_sizes, int n_in,
                              void* d_out, int out_size) {
    const float* x   = (const float*)d_in[0];
    const float* nw  = (const float*)d_in[1];
    const float* ew  = (const float*)d_in[2];
    const float* fw  = (const float*)d_in[3];
    const float* v   = (const float*)d_in[4];
    const float* W1  = (const float*)d_in[5];
    const float* b1  = (const float*)d_in[6];
    const float* W2  = (const float*)d_in[7];
    const float* b2  = (const float*)d_in[8];
    const int*   ei  = (const int*)d_in[9];
    const int*   fc  = (const int*)d_in[10];
    const int*   bid = (const int*)d_in[11];
    float* out = (float*)d_out;

    int flat_off, logit_off;
    if (out_size >= GG * NC + GG * FLATW) { logit_off = 0; flat_off = GG * NC; }
    else if (out_size >= GG * FLATW)      { logit_off = -1; flat_off = 0; }
    else                                  { logit_off = 0; flat_off = -1; }

    k_init<<<NH_B + Z_B + H_B, 256>>>(x, nw, v, ei, fc, bid);
    k_scatter<<<(MM + 255) / 256, 256>>>(ei, fc, bid, ew, fw);
    k_ecc<<<MAXCH, TPB>>>();
    k_gemm1<<<dim3(32, 8), 256>>>(W1, b1, out, flat_off);
    k_gemm2<<<1, 320>>>(W2, b2, out, logit_off);
}

// round 16
// speedup vs baseline: 1.2667x; 1.2667x over previous
#include <cuda_runtime.h>

// Problem constants
#define NN 16000
#define EE 48000
#define FF 32000
#define GG 32
#define DD 64
#define BB 32
#define MM (NN + EE + FF)
#define HID 256
#define NC 10
#define FLATW (BB * DD)   // 2048

// ecc tiling
#define CS    128
#define ECC_Y 4
#define TPB   256
#define MAXCH ((MM + CS - 1) / CS + GG)   // 782
#define STR   39           // band column stride: 3 low pad + 32 + 4 high pad
#define GPQ   4            // graphs per gemm block

// Sigmoid band constants (SIGA = 200/31)
#define C1f   1.577980e-3f   // e^{-SIGA}
#define C2f   2.490021e-6f   // e^{-2 SIGA}
#define EXP2K 9.3077108f     // SIGA * log2(e)

// Device scratch (zero-initialized at load; replay resets by k_gemm2)
__device__ float g_nh[NN * DD];
__device__ int4  g_items[MM];
__device__ int   g_hist[GG];
__device__ int   g_cursor2[GG];
__device__ float g_acc[GG * BB * DD];   // difference-domain accumulators
__device__ float g_h[GG * HID];

// ---------------------------------------------------------------------------
// Fused: nh (float4) + g_acc zero (float4) + graph histogram
#define NH_B 1000   // NN*16/256
#define Z_B  64     // GG*BB*DD/4/256
#define H_B  375    // ceil(MM/256)

__global__ void k_init(const float* __restrict__ x, const float* __restrict__ nw,
                       const float* __restrict__ v,
                       const int* __restrict__ ei, const int* __restrict__ fc,
                       const int* __restrict__ bid) {
    __shared__ int sh[GG];
    int b = blockIdx.x, tid = threadIdx.x;
    if (b < NH_B) {
        int t = b * 256 + tid;            // < NN*16
        int n = t >> 4, c4 = t & 15;
        const float4* vv = (const float4*)v;
        float4 v0 = vv[c4], v1 = vv[16 + c4], v2 = vv[32 + c4];
        float x0 = x[n * 3], x1 = x[n * 3 + 1], x2 = x[n * 3 + 2];
        float w = nw[n];
        float4 r;
        r.x = (x0 * v0.x + x1 * v1.x + x2 * v2.x) * w;
        r.y = (x0 * v0.y + x1 * v1.y + x2 * v2.y) * w;
        r.z = (x0 * v0.z + x1 * v1.z + x2 * v2.z) * w;
        r.w = (x0 * v0.w + x1 * v1.w + x2 * v2.w) * w;
        ((float4*)g_nh)[t] = r;
    } else if (b < NH_B + Z_B) {
        int t = (b - NH_B) * 256 + tid;
        ((float4*)g_acc)[t] = make_float4(0.f, 0.f, 0.f, 0.f);
    } else {
        if (tid < GG) sh[tid] = 0;
        __syncthreads();
        int t = (b - NH_B - Z_B) * 256 + tid;
        if (t < MM) {
            int g;
            if (t < NN)           g = bid[t];
            else if (t < NN + EE) g = bid[ei[t - NN]];
            else                  g = bid[fc[t - NN - EE]];
            atomicAdd(&sh[g], 1);
        }
        __syncthreads();
        if (tid < GG && sh[tid] > 0) atomicAdd(&g_hist[tid], sh[tid]);
    }
}

// Warp-wide inclusive scan over 32 lanes
__device__ __forceinline__ int wscan(int v, int lane) {
    #pragma unroll
    for (int s = 1; s < 32; s <<= 1) {
        int t = __shfl_up_sync(0xFFFFFFFFu, v, s);
        if (lane >= s) v += t;
    }
    return v;
}

// Counting-sort scatter; offsets computed by in-block warp scan of g_hist.
__global__ void k_scatter(const int* __restrict__ ei, const int* __restrict__ fc,
                          const int* __restrict__ bid,
                          const float* __restrict__ ew, const float* __restrict__ fw) {
    __shared__ int scnt[GG];
    __shared__ int sbase[GG];
    __shared__ int soff[GG];
    int tid = threadIdx.x;
    if (tid < 32) {
        int cnt = g_hist[tid];
        int v = wscan(cnt, tid);
        soff[tid] = v - cnt;
        scnt[tid] = 0;
    }
    __syncthreads();
    int t = blockIdx.x * blockDim.x + tid;
    int g = 0, lr = 0;
    int4 it = make_int4(0, 0, 0, 0);
    bool valid = (t < MM);
    if (valid) {
        if (t < NN) {
            g = bid[t];
            int tb = t << 8;
            it = make_int4(tb, tb, tb, __float_as_int(1.0f));
        } else if (t < NN + EE) {
            int e = t - NN;
            int a = ei[e], b = ei[EE + e];
            g = bid[a];
            it = make_int4(a << 8, b << 8, a << 8, __float_as_int(-ew[e]));
        } else {
            int q = t - NN - EE;
            int a = fc[q], b = fc[FF + q], c = fc[2 * FF + q];
            g = bid[a];
            it = make_int4(a << 8, b << 8, c << 8, __float_as_int(fw[q]));
        }
        lr = atomicAdd(&scnt[g], 1);
    }
    __syncthreads();
    if (tid < GG && scnt[tid] > 0)
        sbase[tid] = soff[tid] + atomicAdd(&g_cursor2[tid], scnt[tid]);
    __syncthreads();
    if (valid) g_items[sbase[g] + lr] = it;
}

// ECC kernel: self-resolved chunks, transposed padded band (column layout,
// R9-measured best), 3 sigmoids, 4 difference-domain deltas.
__global__ void __launch_bounds__(TPB) k_ecc() {
    __shared__ float band[TPB * STR];       // 39936 B
    __shared__ int   sck[3];                // {g, start, end}

    int tid = threadIdx.x;
    float4* b4 = (float4*)band;
    for (int i = tid; i < TPB * STR / 4; i += TPB) b4[i] = make_float4(0.f, 0.f, 0.f, 0.f);

    if (tid < 32) {
        int cnt = g_hist[tid];
        int v = wscan(cnt, tid);
        int off = v - cnt;
        int nch = (cnt + CS - 1) / CS;
        int c = wscan(nch, tid);
        int cb = c - nch;
        int bx = blockIdx.x;
        bool own = (bx >= cb) && (bx < cb + nch);
        unsigned m = __ballot_sync(0xFFFFFFFFu, own);
        if (m == 0) {
            if (tid == 0) { sck[0] = 0; sck[1] = 0; sck[2] = 0; }
        } else {
            int src  = __ffs(m) - 1;
            int offg = __shfl_sync(0xFFFFFFFFu, off, src);
            int cbg  = __shfl_sync(0xFFFFFFFFu, cb, src);
            int cntg = __shfl_sync(0xFFFFFFFFu, cnt, src);
            if (tid == 0) {
                int st = offg + (bx - cbg) * CS;
                sck[0] = src; sck[1] = st; sck[2] = min(st + CS, offg + cntg);
            }
        }
    }
    __syncthreads();
    int g = sck[0], start = sck[1], end = sck[2];
    if (start >= end) return;

    int d = tid & 63, y = tid >> 6;
    const char* nb = (const char*)g_nh + d * 4;
    float* col = band + tid * STR;

    for (int i = start + y; i < end; i += ECC_Y) {
        int4 it = g_items[i];
        float s  = (it.w < 0) ? -1.f : 1.f;
        float wa = fabsf(__int_as_float(it.w));
        float h0 = *(const float*)(nb + it.x);
        float h1 = *(const float*)(nb + it.y);
        float h2 = *(const float*)(nb + it.z);
        float h  = fmaxf(h0, fmaxf(h1, h2)) * wa;

        float f  = fmaf(h, 15.5f, 15.5f);        // bump coordinate
        float bf = ceilf(f - 1.5f);              // band rows bf..bf+2
        int   p  = min(max((int)bf, -3), 31) + 3;// physical base row (pads absorb ends)
        float E  = exp2f((f - bf) * EXP2K);      // e^{SIGA*(f-bf)}
        float s0 = __fdividef(s, 1.f + E);       // s * sigmoid(row bf)
        float s1 = __fdividef(s, 1.f + E * C1f);
        float s2 = __fdividef(s, 1.f + E * C2f);

        float* a = col + p;
        a[0] += s0;
        a[1] += s1 - s0;
        a[2] += s2 - s1;
        a[3] += s  - s2;                          // saturation delta
    }
    __syncthreads();

    float* acc = g_acc + g * (BB * DD);
    for (int i = tid; i < BB * DD; i += TPB) {
        int b = i >> 6, dd = i & 63;
        float v = 0.f;
        #pragma unroll
        for (int y2 = 0; y2 < ECC_Y; y2++) {
            const float* c2 = band + (y2 * 64 + dd) * STR;
            v += c2[b + 3];
            if (b == 0) v += c2[0] + c2[1] + c2[2];  // low pad folds into row 0
        }
        atomicAdd(&acc[i], v);
    }
}

// gemm1: finalize flat (prefix over b) + first layer. grid (32, 8) = 256 blocks,
// 8 HID rows per block, 32-lane row dot products (R10-measured best).
__global__ void __launch_bounds__(256) k_gemm1(
        const float* __restrict__ W1, const float* __restrict__ b1,
        float* __restrict__ out, int flat_off) {
    __shared__ float sf[GPQ][FLATW];      // 32KB
    __shared__ float ss[GPQ][4][DD];
    int ht = blockIdx.x, gq = blockIdx.y;
    int tid = threadIdx.x;
    int d = tid & 63, q = tid >> 6;

    float vals[GPQ][8];
    #pragma unroll
    for (int gi = 0; gi < GPQ; gi++) {
        int g = gq * GPQ + gi;
        float run = 0.f;
        #pragma unroll
        for (int k = 0; k < 8; k++) {
            run += g_acc[(g * BB + q * 8 + k) * DD + d];
            vals[gi][k] = run;
        }
        ss[gi][q][d] = run;
    }
    __syncthreads();
    #pragma unroll
    for (int gi = 0; gi < GPQ; gi++) {
        float offp = 0.f;
        for (int r = 0; r < q; r++) offp += ss[gi][r][d];
        #pragma unroll
        for (int k = 0; k < 8; k++) {
            float fv = offp + vals[gi][k];
            sf[gi][(q * 8 + k) * DD + d] = fv;
            if (ht == 0 && flat_off >= 0)
                out[flat_off + (gq * GPQ + gi) * FLATW + (q * 8 + k) * DD + d] = fv;
        }
    }
    __syncthreads();

    int row_l = tid >> 5, lane = tid & 31;
    int row = ht * 8 + row_l;
    const float4* w1v = (const float4*)(W1 + row * FLATW);
    float a0 = 0.f, a1 = 0.f, a2 = 0.f, a3 = 0.f;
    #pragma unroll 4
    for (int j = 0; j < 16; j++) {
        float4 w  = w1v[j * 32 + lane];
        float4 fa = ((const float4*)sf[0])[j * 32 + lane];
        float4 fb = ((const float4*)sf[1])[j * 32 + lane];
        float4 fc2 = ((const float4*)sf[2])[j * 32 + lane];
        float4 fe = ((const float4*)sf[3])[j * 32 + lane];
        a0 += w.x * fa.x + w.y * fa.y + w.z * fa.z + w.w * fa.w;
        a1 += w.x * fb.x + w.y * fb.y + w.z * fb.z + w.w * fb.w;
        a2 += w.x * fc2.x + w.y * fc2.y + w.z * fc2.z + w.w * fc2.w;
        a3 += w.x * fe.x + w.y * fe.y + w.z * fe.z + w.w * fe.w;
    }
    #pragma unroll
    for (int sft = 16; sft >= 1; sft >>= 1) {
        a0 += __shfl_down_sync(0xFFFFFFFFu, a0, sft);
        a1 += __shfl_down_sync(0xFFFFFFFFu, a1, sft);
        a2 += __shfl_down_sync(0xFFFFFFFFu, a2, sft);
        a3 += __shfl_down_sync(0xFFFFFFFFu, a3, sft);
    }
    if (lane == 0) {
        float bb = b1[row];
        int gb = gq * GPQ;
        g_h[(gb + 0) * HID + row] = fmaxf(a0 + bb, 0.f);
        g_h[(gb + 1) * HID + row] = fmaxf(a1 + bb, 0.f);
        g_h[(gb + 2) * HID + row] = fmaxf(a2 + bb, 0.f);
        g_h[(gb + 3) * HID + row] = fmaxf(a3 + bb, 0.f);
    }
}

// gemm2: logits = h @ W2^T + b2. One block, 320 threads. Resets replay state.
__global__ void k_gemm2(const float* __restrict__ W2, const float* __restrict__ b2,
                        float* __restrict__ out, int logit_off) {
    __shared__ float sh[GG][HID + 1];
    __shared__ float sw[NC * HID];
    int tid = threadIdx.x;                // 320
    for (int i = tid; i < GG * HID; i += 320) sh[i >> 8][i & 255] = g_h[i];
    for (int i = tid; i < NC * HID; i += 320) sw[i] = W2[i];
    __syncthreads();
    int c = tid >> 5, g = tid & 31;       // c in 0..9
    float acc = b2[c];
    #pragma unroll 8
    for (int k = 0; k < HID; k++) acc += sh[g][k] * sw[c * HID + k];
    if (logit_off >= 0) out[logit_off + g * NC + c] = acc;
    if (tid < GG) { g_hist[tid] = 0; g_cursor2[tid] = 0; }   // reset for next replay
}

// ---------------------------------------------------------------------------
extern "C" void kernel_launch(void* const* d_in, const int* in_sizes, int n_in,
                              void* d_out, int out_size) {
    const float* x   = (const float*)d_in[0];
    const float* nw  = (const float*)d_in[1];
    const float* ew  = (const float*)d_in[2];
    const float* fw  = (const float*)d_in[3];
    const float* v   = (const float*)d_in[4];
    const float* W1  = (const float*)d_in[5];
    const float* b1  = (const float*)d_in[6];
    const float* W2  = (const float*)d_in[7];
    const float* b2  = (const float*)d_in[8];
    const int*   ei  = (const int*)d_in[9];
    const int*   fc  = (const int*)d_in[10];
    const int*   bid = (const int*)d_in[11];
    float* out = (float*)d_out;

    int flat_off, logit_off;
    if (out_size >= GG * NC + GG * FLATW) { logit_off = 0; flat_off = GG * NC; }
    else if (out_size >= GG * FLATW)      { logit_off = -1; flat_off = 0; }
    else                                  { logit_off = 0; flat_off = -1; }

    k_init<<<NH_B + Z_B + H_B, 256>>>(x, nw, v, ei, fc, bid);
    k_scatter<<<(MM + 255) / 256, 256>>>(ei, fc, bid, ew, fw);
    k_ecc<<<MAXCH, TPB>>>();
    k_gemm1<<<dim3(32, 8), 256>>>(W1, b1, out, flat_off);
    k_gemm2<<<1, 320>>>(W2, b2, out, logit_off);
}

// round 17
// speedup vs baseline: 1.4447x; 1.1405x over previous
#include <cuda_runtime.h>

// Problem constants
#define NN 16000
#define EE 48000
#define FF 32000
#define GG 32
#define DD 64
#define BB 32
#define MM (NN + EE + FF)
#define HID 256
#define NC 10
#define FLATW (BB * DD)   // 2048

// ecc tiling
#define CS    128
#define ECC_Y 4
#define TPB   256
#define MAXCH ((MM + CS - 1) / CS + GG)   // 782
#define NROW  39           // 3 low pad + 32 + 4 high pad band rows
#define GPQ   4            // graphs per gemm block

// Sigmoid band constants (SIGA = 200/31)
#define C1f   1.577980e-3f   // e^{-SIGA}
#define C2f   2.490021e-6f   // e^{-2 SIGA}
#define EXP2K 9.3077108f     // SIGA * log2(e)

// Device scratch (zero-initialized at load; replay resets by k_gemm2)
__device__ float g_nh[NN * DD];
__device__ int4  g_items[MM];
__device__ int   g_hist[GG];
__device__ int   g_cursor2[GG];
__device__ float g_acc[GG * BB * DD];   // difference-domain accumulators
__device__ float g_h[GG * HID];

// ---------------------------------------------------------------------------
// Fused: nh (float4) + g_acc zero (float4) + graph histogram
#define NH_B 1000   // NN*16/256
#define Z_B  64     // GG*BB*DD/4/256
#define H_B  375    // ceil(MM/256)

__global__ void k_init(const float* __restrict__ x, const float* __restrict__ nw,
                       const float* __restrict__ v,
                       const int* __restrict__ ei, const int* __restrict__ fc,
                       const int* __restrict__ bid) {
    __shared__ int sh[GG];
    int b = blockIdx.x, tid = threadIdx.x;
    if (b < NH_B) {
        int t = b * 256 + tid;            // < NN*16
        int n = t >> 4, c4 = t & 15;
        const float4* vv = (const float4*)v;
        float4 v0 = vv[c4], v1 = vv[16 + c4], v2 = vv[32 + c4];
        float x0 = x[n * 3], x1 = x[n * 3 + 1], x2 = x[n * 3 + 2];
        float w = nw[n];
        float4 r;
        r.x = (x0 * v0.x + x1 * v1.x + x2 * v2.x) * w;
        r.y = (x0 * v0.y + x1 * v1.y + x2 * v2.y) * w;
        r.z = (x0 * v0.z + x1 * v1.z + x2 * v2.z) * w;
        r.w = (x0 * v0.w + x1 * v1.w + x2 * v2.w) * w;
        ((float4*)g_nh)[t] = r;
    } else if (b < NH_B + Z_B) {
        int t = (b - NH_B) * 256 + tid;
        ((float4*)g_acc)[t] = make_float4(0.f, 0.f, 0.f, 0.f);
    } else {
        if (tid < GG) sh[tid] = 0;
        __syncthreads();
        int t = (b - NH_B - Z_B) * 256 + tid;
        if (t < MM) {
            int g;
            if (t < NN)           g = bid[t];
            else if (t < NN + EE) g = bid[ei[t - NN]];
            else                  g = bid[fc[t - NN - EE]];
            atomicAdd(&sh[g], 1);
        }
        __syncthreads();
        if (tid < GG && sh[tid] > 0) atomicAdd(&g_hist[tid], sh[tid]);
    }
}

// Warp-wide inclusive scan over 32 lanes
__device__ __forceinline__ int wscan(int v, int lane) {
    #pragma unroll
    for (int s = 1; s < 32; s <<= 1) {
        int t = __shfl_up_sync(0xFFFFFFFFu, v, s);
        if (lane >= s) v += t;
    }
    return v;
}

// Counting-sort scatter; offsets computed by in-block warp scan of g_hist.
__global__ void k_scatter(const int* __restrict__ ei, const int* __restrict__ fc,
                          const int* __restrict__ bid,
                          const float* __restrict__ ew, const float* __restrict__ fw) {
    __shared__ int scnt[GG];
    __shared__ int sbase[GG];
    __shared__ int soff[GG];
    int tid = threadIdx.x;
    if (tid < 32) {
        int cnt = g_hist[tid];
        int v = wscan(cnt, tid);
        soff[tid] = v - cnt;
        scnt[tid] = 0;
    }
    __syncthreads();
    int t = blockIdx.x * blockDim.x + tid;
    int g = 0, lr = 0;
    int4 it = make_int4(0, 0, 0, 0);
    bool valid = (t < MM);
    if (valid) {
        if (t < NN) {
            g = bid[t];
            int tb = t << 8;
            it = make_int4(tb, tb, tb, __float_as_int(1.0f));
        } else if (t < NN + EE) {
            int e = t - NN;
            int a = ei[e], b = ei[EE + e];
            g = bid[a];
            it = make_int4(a << 8, b << 8, a << 8, __float_as_int(-ew[e]));
        } else {
            int q = t - NN - EE;
            int a = fc[q], b = fc[FF + q], c = fc[2 * FF + q];
            g = bid[a];
            it = make_int4(a << 8, b << 8, c << 8, __float_as_int(fw[q]));
        }
        lr = atomicAdd(&scnt[g], 1);
    }
    __syncthreads();
    if (tid < GG && scnt[tid] > 0)
        sbase[tid] = soff[tid] + atomicAdd(&g_cursor2[tid], scnt[tid]);
    __syncthreads();
    if (valid) g_items[sbase[g] + lr] = it;
}

// ECC kernel: row-major band (row stride 256 => bank = tid%32, deterministically
// conflict-free RMWs with immediate offsets), 3 sigmoids, 4 difference deltas.
__global__ void __launch_bounds__(TPB) k_ecc() {
    __shared__ float band[NROW * TPB];      // 39936 B, band[row*256 + tid]
    __shared__ int   sck[3];                // {g, start, end}

    int tid = threadIdx.x;
    float4* b4 = (float4*)band;
    for (int i = tid; i < NROW * TPB / 4; i += TPB) b4[i] = make_float4(0.f, 0.f, 0.f, 0.f);

    if (tid < 32) {
        int cnt = g_hist[tid];
        int v = wscan(cnt, tid);
        int off = v - cnt;
        int nch = (cnt + CS - 1) / CS;
        int c = wscan(nch, tid);
        int cb = c - nch;
        int bx = blockIdx.x;
        bool own = (bx >= cb) && (bx < cb + nch);
        unsigned m = __ballot_sync(0xFFFFFFFFu, own);
        if (m == 0) {
            if (tid == 0) { sck[0] = 0; sck[1] = 0; sck[2] = 0; }
        } else {
            int src  = __ffs(m) - 1;
            int offg = __shfl_sync(0xFFFFFFFFu, off, src);
            int cbg  = __shfl_sync(0xFFFFFFFFu, cb, src);
            int cntg = __shfl_sync(0xFFFFFFFFu, cnt, src);
            if (tid == 0) {
                int st = offg + (bx - cbg) * CS;
                sck[0] = src; sck[1] = st; sck[2] = min(st + CS, offg + cntg);
            }
        }
    }
    __syncthreads();
    int g = sck[0], start = sck[1], end = sck[2];
    if (start >= end) return;

    int d = tid & 63, y = tid >> 6;
    const char* nb = (const char*)g_nh + d * 4;
    float* base = band + tid;

    for (int i = start + y; i < end; i += ECC_Y) {
        int4 it = g_items[i];
        float s  = (it.w < 0) ? -1.f : 1.f;
        float wa = fabsf(__int_as_float(it.w));
        float h0 = *(const float*)(nb + it.x);
        float h1 = *(const float*)(nb + it.y);
        float h2 = *(const float*)(nb + it.z);
        float h  = fmaxf(h0, fmaxf(h1, h2)) * wa;

        float f  = fmaf(h, 15.5f, 15.5f);        // bump coordinate
        float bf = ceilf(f - 1.5f);              // band rows bf..bf+2
        int   p  = min(max((int)bf, -3), 31) + 3;// physical base row (pads absorb ends)
        float E  = exp2f((f - bf) * EXP2K);      // e^{SIGA*(f-bf)}
        float s0 = __fdividef(s, 1.f + E);       // s * sigmoid(row bf)
        float s1 = __fdividef(s, 1.f + E * C1f);
        float s2 = __fdividef(s, 1.f + E * C2f);

        float* a = base + p * TPB;               // one IMAD; imm offsets below
        a[0 * TPB] += s0;
        a[1 * TPB] += s1 - s0;
        a[2 * TPB] += s2 - s1;
        a[3 * TPB] += s  - s2;                   // saturation delta
    }
    __syncthreads();

    float* acc = g_acc + g * (BB * DD);
    for (int i = tid; i < BB * DD; i += TPB) {
        int b = i >> 6, dd = i & 63;
        float v = 0.f;
        #pragma unroll
        for (int y2 = 0; y2 < ECC_Y; y2++) {
            int t2 = y2 * 64 + dd;
            v += band[(b + 3) * TPB + t2];
            if (b == 0) v += band[t2] + band[TPB + t2] + band[2 * TPB + t2];
        }
        atomicAdd(&acc[i], v);
    }
}

// gemm1: finalize flat (prefix over b) + first layer. grid (32, 8) = 256 blocks,
// 8 HID rows per block, 32-lane row dot products (R10/R16-measured best).
__global__ void __launch_bounds__(256) k_gemm1(
        const float* __restrict__ W1, const float* __restrict__ b1,
        float* __restrict__ out, int flat_off) {
    __shared__ float sf[GPQ][FLATW];      // 32KB
    __shared__ float ss[GPQ][4][DD];
    int ht = blockIdx.x, gq = blockIdx.y;
    int tid = threadIdx.x;
    int d = tid & 63, q = tid >> 6;

    float vals[GPQ][8];
    #pragma unroll
    for (int gi = 0; gi < GPQ; gi++) {
        int g = gq * GPQ + gi;
        float run = 0.f;
        #pragma unroll
        for (int k = 0; k < 8; k++) {
            run += g_acc[(g * BB + q * 8 + k) * DD + d];
            vals[gi][k] = run;
        }
        ss[gi][q][d] = run;
    }
    __syncthreads();
    #pragma unroll
    for (int gi = 0; gi < GPQ; gi++) {
        float offp = 0.f;
        for (int r = 0; r < q; r++) offp += ss[gi][r][d];
        #pragma unroll
        for (int k = 0; k < 8; k++) {
            float fv = offp + vals[gi][k];
            sf[gi][(q * 8 + k) * DD + d] = fv;
            if (ht == 0 && flat_off >= 0)
                out[flat_off + (gq * GPQ + gi) * FLATW + (q * 8 + k) * DD + d] = fv;
        }
    }
    __syncthreads();

    int row_l = tid >> 5, lane = tid & 31;
    int row = ht * 8 + row_l;
    const float4* w1v = (const float4*)(W1 + row * FLATW);
    float a0 = 0.f, a1 = 0.f, a2 = 0.f, a3 = 0.f;
    #pragma unroll 4
    for (int j = 0; j < 16; j++) {
        float4 w  = w1v[j * 32 + lane];
        float4 fa = ((const float4*)sf[0])[j * 32 + lane];
        float4 fb = ((const float4*)sf[1])[j * 32 + lane];
        float4 fc2 = ((const float4*)sf[2])[j * 32 + lane];
        float4 fe = ((const float4*)sf[3])[j * 32 + lane];
        a0 += w.x * fa.x + w.y * fa.y + w.z * fa.z + w.w * fa.w;
        a1 += w.x * fb.x + w.y * fb.y + w.z * fb.z + w.w * fb.w;
        a2 += w.x * fc2.x + w.y * fc2.y + w.z * fc2.z + w.w * fc2.w;
        a3 += w.x * fe.x + w.y * fe.y + w.z * fe.z + w.w * fe.w;
    }
    #pragma unroll
    for (int sft = 16; sft >= 1; sft >>= 1) {
        a0 += __shfl_down_sync(0xFFFFFFFFu, a0, sft);
        a1 += __shfl_down_sync(0xFFFFFFFFu, a1, sft);
        a2 += __shfl_down_sync(0xFFFFFFFFu, a2, sft);
        a3 += __shfl_down_sync(0xFFFFFFFFu, a3, sft);
    }
    if (lane == 0) {
        float bb = b1[row];
        int gb = gq * GPQ;
        g_h[(gb + 0) * HID + row] = fmaxf(a0 + bb, 0.f);
        g_h[(gb + 1) * HID + row] = fmaxf(a1 + bb, 0.f);
        g_h[(gb + 2) * HID + row] = fmaxf(a2 + bb, 0.f);
        g_h[(gb + 3) * HID + row] = fmaxf(a3 + bb, 0.f);
    }
}

// gemm2: logits = h @ W2^T + b2. One block, 320 threads. Resets replay state.
__global__ void k_gemm2(const float* __restrict__ W2, const float* __restrict__ b2,
                        float* __restrict__ out, int logit_off) {
    __shared__ float sh[GG][HID + 1];
    __shared__ float sw[NC * HID];
    int tid = threadIdx.x;                // 320
    for (int i = tid; i < GG * HID; i += 320) sh[i >> 8][i & 255] = g_h[i];
    for (int i = tid; i < NC * HID; i += 320) sw[i] = W2[i];
    __syncthreads();
    int c = tid >> 5, g = tid & 31;       // c in 0..9
    float acc = b2[c];
    #pragma unroll 8
    for (int k = 0; k < HID; k++) acc += sh[g][k] * sw[c * HID + k];
    if (logit_off >= 0) out[logit_off + g * NC + c] = acc;
    if (tid < GG) { g_hist[tid] = 0; g_cursor2[tid] = 0; }   // reset for next replay
}

// ---------------------------------------------------------------------------
extern "C" void kernel_launch(void* const* d_in, const int* in_sizes, int n_in,
                              void* d_out, int out_size) {
    const float* x   = (const float*)d_in[0];
    const float* nw  = (const float*)d_in[1];
    const float* ew  = (const float*)d_in[2];
    const float* fw  = (const float*)d_in[3];
    const float* v   = (const float*)d_in[4];
    const float* W1  = (const float*)d_in[5];
    const float* b1  = (const float*)d_in[6];
    const float* W2  = (const float*)d_in[7];
    const float* b2  = (const float*)d_in[8];
    const int*   ei  = (const int*)d_in[9];
    const int*   fc  = (const int*)d_in[10];
    const int*   bid = (const int*)d_in[11];
    float* out = (float*)d_out;

    int flat_off, logit_off;
    if (out_size >= GG * NC + GG * FLATW) { logit_off = 0; flat_off = GG * NC; }
    else if (out_size >= GG * FLATW)      { logit_off = -1; flat_off = 0; }
    else                                  { logit_off = 0; flat_off = -1; }

    k_init<<<NH_B + Z_B + H_B, 256>>>(x, nw, v, ei, fc, bid);
    k_scatter<<<(MM + 255) / 256, 256>>>(ei, fc, bid, ew, fw);
    k_ecc<<<MAXCH, TPB>>>();
    k_gemm1<<<dim3(32, 8), 256>>>(W1, b1, out, flat_off);
    k_gemm2<<<1, 320>>>(W2, b2, out, logit_off);
}